// round 6
// baseline (speedup 1.0000x reference)
#include <cuda_runtime.h>

#define NTOT 12544   // 16 * 784 flattened spatial*batch
#define HWSZ 784
#define WD   28

// ---------------- scratch (device globals; no allocation allowed) ----------
__device__ float g_xT [512 * NTOT];
__device__ float g_t3 [512 * NTOT];
__device__ float g_t1a[128 * NTOT]; __device__ float g_t1b[128 * NTOT];
__device__ float g_u1a[128 * NTOT]; __device__ float g_u1b[128 * NTOT];
__device__ float g_t2a[128 * NTOT]; __device__ float g_t2b[128 * NTOT];
__device__ float g_u2a[128 * NTOT]; __device__ float g_u2b[128 * NTOT];
__device__ float g_q1T [512 * 128];   // quantized w1s, k-major
__device__ float g_w1aT[128 * 128];   // w1a k-major, NEGATED
__device__ float g_q2T [1152 * 128];
__device__ float g_w2aT[1152 * 128];  // negated
__device__ float g_q3T [128 * 512];
__device__ float g_w3aT[512 * 512];   // negated
__device__ float g_inv1[128], g_bias1[128], g_inv2[128], g_bias2[128];

template<int ID>
__device__ __forceinline__ float* gbuf(float* rt) {
    if constexpr (ID == 0) return g_xT;
    else if constexpr (ID == 1) return g_t3;
    else if constexpr (ID == 2) return g_t1a;
    else if constexpr (ID == 3) return g_t1b;
    else if constexpr (ID == 4) return g_u1a;
    else if constexpr (ID == 5) return g_u1b;
    else if constexpr (ID == 6) return g_t2a;
    else if constexpr (ID == 7) return g_t2b;
    else if constexpr (ID == 8) return g_u2a;
    else if constexpr (ID == 9) return g_u2b;
    else if constexpr (ID == 10) return g_q1T;
    else if constexpr (ID == 11) return g_w1aT;
    else if constexpr (ID == 12) return g_q2T;
    else if constexpr (ID == 13) return g_w2aT;
    else if constexpr (ID == 14) return g_q3T;
    else if constexpr (ID == 15) return g_w3aT;
    else return rt;
}

// ---- weight prep (quantize/negate + k-major transpose), one kernel --------
__device__ __forceinline__ void wp_one(const float* src, float* dst,
                                       int i, int M, int K, int quant, int neg) {
    int m = i / K, k = i - m * K;
    float w = src[i];
    float q = w;
    if (quant) {
        float a = fabsf(w) + 1e-8f;
        q = copysignf(exp2f(rintf(log2f(a))), w);
        if (w == 0.0f) q = 0.0f;   // jnp.sign(0) == 0
    }
    if (neg) q = -q;
    dst[k * M + m] = q;
}

__global__ void wprep_all(const float* __restrict__ w1s, const float* __restrict__ w1a,
                          const float* __restrict__ w2s, const float* __restrict__ w2a,
                          const float* __restrict__ w3s, const float* __restrict__ w3a) {
    int gid = blockIdx.x * blockDim.x + threadIdx.x;
    if (gid < 65536)                 wp_one(w1s, g_q1T,  gid,          128, 512,  1, 0);
    else if (gid < 81920)            wp_one(w1a, g_w1aT, gid - 65536,  128, 128,  0, 1);
    else if (gid < 229376)           wp_one(w2s, g_q2T,  gid - 81920,  128, 1152, 1, 0);
    else if (gid < 376832)           wp_one(w2a, g_w2aT, gid - 229376, 128, 1152, 0, 1);
    else if (gid < 442368)           wp_one(w3s, g_q3T,  gid - 376832, 512, 128,  1, 0);
    else if (gid < 704512)           wp_one(w3a, g_w3aT, gid - 442368, 512, 512,  0, 1);
}

__global__ void bnprep(const float* g1, const float* b1, const float* m1, const float* v1,
                       const float* g2, const float* b2, const float* m2, const float* v2) {
    int i = threadIdx.x;
    if (i < 128) {
        float inv = g1[i] * rsqrtf(v1[i] + 1e-5f);
        g_inv1[i] = inv; g_bias1[i] = b1[i] - m1[i] * inv;
        float inv2 = g2[i] * rsqrtf(v2[i] + 1e-5f);
        g_inv2[i] = inv2; g_bias2[i] = b2[i] - m2[i] * inv2;
    }
}

// -------- x: NCHW -> [c][b*784+hw] ----------------------------------------
__global__ void transpose_x(const float* __restrict__ x) {
    int i = blockIdx.x * blockDim.x + threadIdx.x;
    if (i >= 512 * (NTOT / 4)) return;
    int c  = i / (NTOT / 4);
    int r  = i - c * (NTOT / 4);
    int n  = r * 4;
    int b  = n / HWSZ;
    int hw = n - b * HWSZ;
    float4 v = ((const float4*)x)[((b * 512 + c) * HWSZ + hw) >> 2];
    ((float4*)g_xT)[i] = v;
}

// ---------------------------------------------------------------------------
// GEMM-shaped kernel, split-K aware. BN=128, NT=(BM/TM)*16 threads.
// A duplicated in smem -> LDS.128 gives ready {a,a} pairs.
//   MODE 0: acc += a*b      MODE 1: acc += |b-a| (A negated)
//   CONV 0: 1x1 fill        CONV 1: implicit 3x3 fill, zero halo (BK=18)
//   FILL 0: X0 plain        FILL 1: X0+X1        FILL 2: relu(bias-inv*(X0+X1))
//   BNSEL: which inv/bias arrays for FILL 2 (1 or 2)
//   EPI 0: raw acc store    EPI 2: relu(bn3(-acc)+resid) NCHW store
// ---------------------------------------------------------------------------
template<int BM, int TM, int BK, int MODE, int CONV, int FILL, int BNSEL,
         int EPI, int WID, int X0ID, int X1ID, int YID>
__global__ void __launch_bounds__((BM/TM)*16)
gx(float* Yrt, int Mtot, int K, int kbase,
   const float* __restrict__ bg, const float* __restrict__ bb,
   const float* __restrict__ bm, const float* __restrict__ bv,
   const float* __restrict__ resid)
{
    constexpr int BN = 128;
    constexpr int NT = (BM / TM) * 16;
    static_assert(CONV == 0 || NT == 128, "conv fill assumes 128 threads");
    constexpr int AF4 = BK * BM / 4;
    constexpr int AU  = (AF4 + NT - 1) / NT;
    constexpr int BU  = CONV ? 1 : (BK * BN / 4 / NT);
    const float* Wt = gbuf<WID>(nullptr);
    const float* X0 = gbuf<X0ID>(nullptr);
    const float* X1 = gbuf<X1ID>(nullptr);
    const float* binv  = (BNSEL == 1) ? g_inv1  : g_inv2;
    const float* bbias = (BNSEL == 1) ? g_bias1 : g_bias2;
    float* Y = gbuf<YID>(Yrt);

    __shared__ __align__(16) float As[2][BK * BM * 2];   // duplicated
    __shared__ __align__(16) float Bs[2][BK * BN];

    int tid = threadIdx.x;
    int tx  = tid % 16;
    int ty  = tid / 16;
    int m0  = blockIdx.y * BM;
    int n0  = blockIdx.x * BN;

    int cn = n0 + (tid & 127);
    int cw = cn % WD;
    int ch = (cn / WD) % WD;

    float4 pa[AU];
    float4 pb[BU];
    float  pc[CONV ? 18 : 1];

    auto loadA = [&](int k0) {
#pragma unroll
        for (int u = 0; u < AU; u++) {
            int v = tid + u * NT;
            if (AF4 % NT == 0 || v < AF4) {
                int kk = v / (BM / 4), mq = v - kk * (BM / 4);
                pa[u] = *(const float4*)&Wt[(kbase + k0 + kk) * Mtot + m0 + mq * 4];
            }
        }
    };
    auto storeA = [&](int buf) {
#pragma unroll
        for (int u = 0; u < AU; u++) {
            int v = tid + u * NT;
            if (AF4 % NT == 0 || v < AF4) {
                int kk = v / (BM / 4), mq = v - kk * (BM / 4);
                float* d = &As[buf][kk * BM * 2 + mq * 8];
                *(float4*)(d)     = make_float4(pa[u].x, pa[u].x, pa[u].y, pa[u].y);
                *(float4*)(d + 4) = make_float4(pa[u].z, pa[u].z, pa[u].w, pa[u].w);
            }
        }
    };
    auto loadB = [&](int k0) {
        if (CONV == 0) {
#pragma unroll
            for (int u = 0; u < BU; u++) {
                int v = tid + u * NT;
                int kk = v / (BN / 4), nq = v - kk * (BN / 4);
                int row = kbase + k0 + kk;
                long off = (long)row * NTOT + n0 + nq * 4;
                float4 a = *(const float4*)&X0[off];
                if (FILL >= 1) {
                    float4 b = *(const float4*)&X1[off];
                    a.x += b.x; a.y += b.y; a.z += b.z; a.w += b.w;
                }
                if (FILL == 2) {
                    float iv = binv[row], bs = bbias[row];
                    a.x = fmaxf(fmaf(a.x, -iv, bs), 0.0f);
                    a.y = fmaxf(fmaf(a.y, -iv, bs), 0.0f);
                    a.z = fmaxf(fmaf(a.z, -iv, bs), 0.0f);
                    a.w = fmaxf(fmaf(a.w, -iv, bs), 0.0f);
                }
                pb[u] = a;
            }
        } else {
            int c0 = (kbase + k0) / 9;
#pragma unroll
            for (int half = 0; half < 2; half++) {
                int c = c0 + half;
#pragma unroll
                for (int q = 0; q < 9; q++) {
                    const int r = q / 3, s = q % 3;
                    int hh = ch + r - 1, ww = cw + s - 1;
                    float val = 0.0f;
                    if (hh >= 0 && hh < WD && ww >= 0 && ww < WD) {
                        long off = (long)c * NTOT + cn + (r - 1) * WD + (s - 1);
                        val = X0[off];
                        if (FILL >= 1) val += X1[off];
                        if (FILL == 2)
                            val = fmaxf(fmaf(val, -binv[c], bbias[c]), 0.0f);
                    }
                    pc[half * 9 + q] = val;
                }
            }
        }
    };
    auto storeB = [&](int buf) {
        if (CONV == 0) {
#pragma unroll
            for (int u = 0; u < BU; u++) {
                int v = tid + u * NT;
                int kk = v / (BN / 4), nq = v - kk * (BN / 4);
                *(float4*)&Bs[buf][kk * BN + nq * 4] = pb[u];
            }
        } else {
#pragma unroll
            for (int half = 0; half < 2; half++)
#pragma unroll
                for (int q = 0; q < 9; q++)
                    Bs[buf][(half * 9 + q) * BN + (tid & 127)] = pc[half * 9 + q];
        }
    };

    unsigned long long acc2[TM][4];
#pragma unroll
    for (int i = 0; i < TM; i++)
#pragma unroll
        for (int j = 0; j < 4; j++) acc2[i][j] = 0ULL;

    loadA(0); loadB(0);
    storeA(0); storeB(0);
    __syncthreads();

    int T = K / BK;
    for (int t = 0; t < T; t++) {
        int buf = t & 1;
        if (t + 1 < T) { loadA((t + 1) * BK); loadB((t + 1) * BK); }

#pragma unroll
        for (int kk = 0; kk < BK; kk++) {
            unsigned long long ad[TM];
#pragma unroll
            for (int h = 0; h < TM / 2; h++) {
                ulonglong2 p = *(const ulonglong2*)
                    &As[buf][kk * BM * 2 + ty * TM * 2 + h * 4];
                ad[2 * h] = p.x; ad[2 * h + 1] = p.y;
            }
            unsigned long long b2[4];
            {
                ulonglong2 p0 = *(const ulonglong2*)&Bs[buf][kk * BN + tx * 8];
                ulonglong2 p1 = *(const ulonglong2*)&Bs[buf][kk * BN + tx * 8 + 4];
                b2[0] = p0.x; b2[1] = p0.y; b2[2] = p1.x; b2[3] = p1.y;
            }
#pragma unroll
            for (int i = 0; i < TM; i++)
#pragma unroll
                for (int jp = 0; jp < 4; jp++) {
                    if (MODE == 0) {
                        asm("fma.rn.f32x2 %0, %1, %2, %0;"
                            : "+l"(acc2[i][jp]) : "l"(ad[i]), "l"(b2[jp]));
                    } else {
                        unsigned long long d;
                        asm("add.rn.f32x2 %0, %1, %2;"
                            : "=l"(d) : "l"(b2[jp]), "l"(ad[i]));
                        d &= 0x7FFFFFFF7FFFFFFFULL;
                        asm("add.rn.f32x2 %0, %0, %1;"
                            : "+l"(acc2[i][jp]) : "l"(d));
                    }
                }
        }

        if (t + 1 < T) { storeA(buf ^ 1); storeB(buf ^ 1); }
        __syncthreads();
    }

    float accf[TM][8];
#pragma unroll
    for (int i = 0; i < TM; i++)
#pragma unroll
        for (int jp = 0; jp < 4; jp++)
            asm("mov.b64 {%0, %1}, %2;"
                : "=f"(accf[i][2*jp]), "=f"(accf[i][2*jp+1]) : "l"(acc2[i][jp]));

#pragma unroll
    for (int i = 0; i < TM; i++) {
        int m = m0 + ty * TM + i;
        if (EPI == 2) {
            float inv  = bg[m] * rsqrtf(bv[m] + 1e-5f);
            float bias = bb[m] - bm[m] * inv;
#pragma unroll
            for (int j = 0; j < 8; j++) {
                int n   = n0 + tx * 8 + j;
                int b_  = n / HWSZ;
                int hw  = n - b_ * HWSZ;
                int idx = (b_ * 512 + m) * HWSZ + hw;
                float v = fmaf(accf[i][j], -inv, bias) + resid[idx];
                Y[idx] = fmaxf(v, 0.0f);
            }
        } else {
            int base = m * NTOT + n0 + tx * 8;
            *(float4*)&Y[base]     = make_float4(accf[i][0], accf[i][1],
                                                 accf[i][2], accf[i][3]);
            *(float4*)&Y[base + 4] = make_float4(accf[i][4], accf[i][5],
                                                 accf[i][6], accf[i][7]);
        }
    }
}

// ---------------------------------------------------------------------------
extern "C" void kernel_launch(void* const* d_in, const int* in_sizes, int n_in,
                              void* d_out, int out_size) {
    const float* x   = (const float*)d_in[0];
    const float* w1s = (const float*)d_in[1];
    const float* w1a = (const float*)d_in[2];
    const float* w2s = (const float*)d_in[3];
    const float* w2a = (const float*)d_in[4];
    const float* w3s = (const float*)d_in[5];
    const float* w3a = (const float*)d_in[6];
    const float* g1 = (const float*)d_in[7],  *b1 = (const float*)d_in[8];
    const float* m1 = (const float*)d_in[9],  *v1 = (const float*)d_in[10];
    const float* g2 = (const float*)d_in[11], *b2 = (const float*)d_in[12];
    const float* m2 = (const float*)d_in[13], *v2 = (const float*)d_in[14];
    const float* g3 = (const float*)d_in[15], *b3 = (const float*)d_in[16];
    const float* m3 = (const float*)d_in[17], *v3 = (const float*)d_in[18];
    float* out = (float*)d_out;

    wprep_all<<<(704512 + 255) / 256, 256>>>(w1s, w1a, w2s, w2a, w3s, w3a);
    bnprep<<<1, 128>>>(g1, b1, m1, v1, g2, b2, m2, v2);
    transpose_x<<<(512 * (NTOT / 4) + 255) / 256, 256>>>(x);

    dim3 gsm(98, 4);   // M=128 stages, BM=32
    dim3 gbg(98, 8);   // M=512 stages, BM=64

    // stage 1 shift: K=512 split 2x256 -> t1a,t1b
    gx<32,4,16, 0,0,0,0, 0, 10,0,0, 2><<<gsm,128>>>(nullptr,128,256,0,  nullptr,nullptr,nullptr,nullptr,nullptr);
    gx<32,4,16, 0,0,0,0, 0, 10,0,0, 3><<<gsm,128>>>(nullptr,128,256,256,nullptr,nullptr,nullptr,nullptr,nullptr);
    // stage 1 adder: B = t1a+t1b, K=128 split 2x64 -> u1a,u1b (raw partials)
    gx<32,4,16, 1,0,1,0, 0, 11,2,3, 4><<<gsm,128>>>(nullptr,128,64,0,  nullptr,nullptr,nullptr,nullptr,nullptr);
    gx<32,4,16, 1,0,1,0, 0, 11,2,3, 5><<<gsm,128>>>(nullptr,128,64,64, nullptr,nullptr,nullptr,nullptr,nullptr);
    // stage 2 shift (3x3): B = relu(bn1(-(u1a+u1b))), K=1152 split 2x576 -> t2a,t2b
    gx<32,4,18, 0,1,2,1, 0, 12,4,5, 6><<<gsm,128>>>(nullptr,128,576,0,  nullptr,nullptr,nullptr,nullptr,nullptr);
    gx<32,4,18, 0,1,2,1, 0, 12,4,5, 7><<<gsm,128>>>(nullptr,128,576,576,nullptr,nullptr,nullptr,nullptr,nullptr);
    // stage 2 adder (3x3): B = t2a+t2b, K=1152 split 2x576 -> u2a,u2b
    gx<32,4,18, 1,1,1,0, 0, 13,6,7, 8><<<gsm,128>>>(nullptr,128,576,0,  nullptr,nullptr,nullptr,nullptr,nullptr);
    gx<32,4,18, 1,1,1,0, 0, 13,6,7, 9><<<gsm,128>>>(nullptr,128,576,576,nullptr,nullptr,nullptr,nullptr,nullptr);
    // stage 3 shift: B = relu(bn2(-(u2a+u2b))), M=512, K=128 -> t3
    gx<64,8,16, 0,0,2,2, 0, 14,8,9, 1><<<gbg,128>>>(nullptr,512,128,0, nullptr,nullptr,nullptr,nullptr,nullptr);
    // stage 3 adder: B = t3, K=512, bn3 + resid + relu -> out (NCHW)
    gx<64,8,16, 1,0,0,0, 2, 15,1,1, -1><<<gbg,128>>>(out,512,512,0, g3,b3,m3,v3, x);
}

// round 7
// speedup vs baseline: 1.0029x; 1.0029x over previous
#include <cuda_runtime.h>

#define NTOT 12544   // 16 * 784 flattened spatial*batch
#define HWSZ 784
#define WD   28

// ---------------- scratch (device globals; no allocation allowed) ----------
__device__ float g_xT [512 * NTOT];
__device__ float g_t3 [512 * NTOT];
__device__ float g_t1a[128 * NTOT]; __device__ float g_t1b[128 * NTOT];
__device__ float g_u1a[128 * NTOT]; __device__ float g_u1b[128 * NTOT];
__device__ float g_t2a[128 * NTOT]; __device__ float g_t2b[128 * NTOT];
__device__ float g_u2a[128 * NTOT]; __device__ float g_u2b[128 * NTOT];
__device__ float g_q1T [512 * 128];   // quantized w1s, k-major
__device__ float g_w1aT[128 * 128];   // w1a k-major, NEGATED
__device__ float g_q2T [1152 * 128];
__device__ float g_w2aT[1152 * 128];  // negated
__device__ float g_q3T [128 * 512];
__device__ float g_w3aT[512 * 512];   // negated
__device__ float g_inv1[128], g_bias1[128], g_inv2[128], g_bias2[128];

template<int ID>
__device__ __forceinline__ float* gbuf(float* rt) {
    if constexpr (ID == 0) return g_xT;
    else if constexpr (ID == 1) return g_t3;
    else if constexpr (ID == 2) return g_t1a;
    else if constexpr (ID == 3) return g_t1b;
    else if constexpr (ID == 4) return g_u1a;
    else if constexpr (ID == 5) return g_u1b;
    else if constexpr (ID == 6) return g_t2a;
    else if constexpr (ID == 7) return g_t2b;
    else if constexpr (ID == 8) return g_u2a;
    else if constexpr (ID == 9) return g_u2b;
    else if constexpr (ID == 10) return g_q1T;
    else if constexpr (ID == 11) return g_w1aT;
    else if constexpr (ID == 12) return g_q2T;
    else if constexpr (ID == 13) return g_w2aT;
    else if constexpr (ID == 14) return g_q3T;
    else if constexpr (ID == 15) return g_w3aT;
    else return rt;
}

// ---- weight prep (quantize/negate + k-major transpose), one kernel --------
__device__ __forceinline__ void wp_one(const float* src, float* dst,
                                       int i, int M, int K, int quant, int neg) {
    int m = i / K, k = i - m * K;
    float w = src[i];
    float q = w;
    if (quant) {
        float a = fabsf(w) + 1e-8f;
        q = copysignf(exp2f(rintf(log2f(a))), w);
        if (w == 0.0f) q = 0.0f;   // jnp.sign(0) == 0
    }
    if (neg) q = -q;
    dst[k * M + m] = q;
}

__global__ void wprep_all(const float* __restrict__ w1s, const float* __restrict__ w1a,
                          const float* __restrict__ w2s, const float* __restrict__ w2a,
                          const float* __restrict__ w3s, const float* __restrict__ w3a) {
    int gid = blockIdx.x * blockDim.x + threadIdx.x;
    if (gid < 65536)                 wp_one(w1s, g_q1T,  gid,          128, 512,  1, 0);
    else if (gid < 81920)            wp_one(w1a, g_w1aT, gid - 65536,  128, 128,  0, 1);
    else if (gid < 229376)           wp_one(w2s, g_q2T,  gid - 81920,  128, 1152, 1, 0);
    else if (gid < 376832)           wp_one(w2a, g_w2aT, gid - 229376, 128, 1152, 0, 1);
    else if (gid < 442368)           wp_one(w3s, g_q3T,  gid - 376832, 512, 128,  1, 0);
    else if (gid < 704512)           wp_one(w3a, g_w3aT, gid - 442368, 512, 512,  0, 1);
}

__global__ void bnprep(const float* g1, const float* b1, const float* m1, const float* v1,
                       const float* g2, const float* b2, const float* m2, const float* v2) {
    int i = threadIdx.x;
    if (i < 128) {
        float inv = g1[i] * rsqrtf(v1[i] + 1e-5f);
        g_inv1[i] = inv; g_bias1[i] = b1[i] - m1[i] * inv;
        float inv2 = g2[i] * rsqrtf(v2[i] + 1e-5f);
        g_inv2[i] = inv2; g_bias2[i] = b2[i] - m2[i] * inv2;
    }
}

// -------- x: NCHW -> [c][b*784+hw] ----------------------------------------
__global__ void transpose_x(const float* __restrict__ x) {
    int i = blockIdx.x * blockDim.x + threadIdx.x;
    if (i >= 512 * (NTOT / 4)) return;
    int c  = i / (NTOT / 4);
    int r  = i - c * (NTOT / 4);
    int n  = r * 4;
    int b  = n / HWSZ;
    int hw = n - b * HWSZ;
    float4 v = ((const float4*)x)[((b * 512 + c) * HWSZ + hw) >> 2];
    ((float4*)g_xT)[i] = v;
}

// ---------------------------------------------------------------------------
// GEMM-shaped kernel, split-K via blockIdx.z (co-resident halves).
// BN=128, NT=(BM/TM)*16 threads. A duplicated in smem -> ready {a,a} pairs.
//   MODE 0: acc += a*b      MODE 1: acc += |b-a| (A negated)
//   CONV 0: 1x1 fill        CONV 1: implicit 3x3 fill, zero halo (BK=18)
//   FILL 0: X0 plain        FILL 1: X0+X1        FILL 2: relu(bias-inv*(X0+X1))
//   BNSEL: inv/bias arrays for FILL 2 (1 or 2)
//   EPI 0: raw acc -> Y[z]  EPI 2: relu(bn3(-acc)+resid) NCHW store
// K = per-z K chunk; kbase = blockIdx.z * K.
// ---------------------------------------------------------------------------
template<int BM, int TM, int BK, int MODE, int CONV, int FILL, int BNSEL,
         int EPI, int WID, int X0ID, int X1ID, int Y0ID, int Y1ID>
__global__ void __launch_bounds__((BM/TM)*16)
gx(float* Yrt, int Mtot, int K,
   const float* __restrict__ bg, const float* __restrict__ bb,
   const float* __restrict__ bm, const float* __restrict__ bv,
   const float* __restrict__ resid)
{
    constexpr int BN = 128;
    constexpr int NT = (BM / TM) * 16;
    static_assert(CONV == 0 || NT == 128, "conv fill assumes 128 threads");
    constexpr int AF4 = BK * BM / 4;
    constexpr int AU  = (AF4 + NT - 1) / NT;
    constexpr int BU  = CONV ? 1 : (BK * BN / 4 / NT);
    const float* Wt = gbuf<WID>(nullptr);
    const float* X0 = gbuf<X0ID>(nullptr);
    const float* X1 = gbuf<X1ID>(nullptr);
    const float* binv  = (BNSEL == 1) ? g_inv1  : g_inv2;
    const float* bbias = (BNSEL == 1) ? g_bias1 : g_bias2;
    int zz = blockIdx.z;
    int kbase = zz * K;
    float* Y = zz ? gbuf<Y1ID>(Yrt) : gbuf<Y0ID>(Yrt);

    __shared__ __align__(16) float As[2][BK * BM * 2];   // duplicated
    __shared__ __align__(16) float Bs[2][BK * BN];

    int tid = threadIdx.x;
    int tx  = tid % 16;
    int ty  = tid / 16;
    int m0  = blockIdx.y * BM;
    int n0  = blockIdx.x * BN;

    int cn = n0 + (tid & 127);
    int cw = cn % WD;
    int ch = (cn / WD) % WD;

    float4 pa[AU];
    float4 pb[BU];
    float  pc[CONV ? 18 : 1];

    auto loadA = [&](int k0) {
#pragma unroll
        for (int u = 0; u < AU; u++) {
            int v = tid + u * NT;
            if (AF4 % NT == 0 || v < AF4) {
                int kk = v / (BM / 4), mq = v - kk * (BM / 4);
                pa[u] = *(const float4*)&Wt[(kbase + k0 + kk) * Mtot + m0 + mq * 4];
            }
        }
    };
    auto storeA = [&](int buf) {
#pragma unroll
        for (int u = 0; u < AU; u++) {
            int v = tid + u * NT;
            if (AF4 % NT == 0 || v < AF4) {
                int kk = v / (BM / 4), mq = v - kk * (BM / 4);
                float* d = &As[buf][kk * BM * 2 + mq * 8];
                *(float4*)(d)     = make_float4(pa[u].x, pa[u].x, pa[u].y, pa[u].y);
                *(float4*)(d + 4) = make_float4(pa[u].z, pa[u].z, pa[u].w, pa[u].w);
            }
        }
    };
    auto loadB = [&](int k0) {
        if (CONV == 0) {
#pragma unroll
            for (int u = 0; u < BU; u++) {
                int v = tid + u * NT;
                int kk = v / (BN / 4), nq = v - kk * (BN / 4);
                int row = kbase + k0 + kk;
                long off = (long)row * NTOT + n0 + nq * 4;
                float4 a = *(const float4*)&X0[off];
                if (FILL >= 1) {
                    float4 b = *(const float4*)&X1[off];
                    a.x += b.x; a.y += b.y; a.z += b.z; a.w += b.w;
                }
                if (FILL == 2) {
                    float iv = binv[row], bs = bbias[row];
                    a.x = fmaxf(fmaf(a.x, -iv, bs), 0.0f);
                    a.y = fmaxf(fmaf(a.y, -iv, bs), 0.0f);
                    a.z = fmaxf(fmaf(a.z, -iv, bs), 0.0f);
                    a.w = fmaxf(fmaf(a.w, -iv, bs), 0.0f);
                }
                pb[u] = a;
            }
        } else {
            int c0 = (kbase + k0) / 9;
#pragma unroll
            for (int half = 0; half < 2; half++) {
                int c = c0 + half;
#pragma unroll
                for (int q = 0; q < 9; q++) {
                    const int r = q / 3, s = q % 3;
                    int hh = ch + r - 1, ww = cw + s - 1;
                    float val = 0.0f;
                    if (hh >= 0 && hh < WD && ww >= 0 && ww < WD) {
                        long off = (long)c * NTOT + cn + (r - 1) * WD + (s - 1);
                        val = X0[off];
                        if (FILL >= 1) val += X1[off];
                        if (FILL == 2)
                            val = fmaxf(fmaf(val, -binv[c], bbias[c]), 0.0f);
                    }
                    pc[half * 9 + q] = val;
                }
            }
        }
    };
    auto storeB = [&](int buf) {
        if (CONV == 0) {
#pragma unroll
            for (int u = 0; u < BU; u++) {
                int v = tid + u * NT;
                int kk = v / (BN / 4), nq = v - kk * (BN / 4);
                *(float4*)&Bs[buf][kk * BN + nq * 4] = pb[u];
            }
        } else {
#pragma unroll
            for (int half = 0; half < 2; half++)
#pragma unroll
                for (int q = 0; q < 9; q++)
                    Bs[buf][(half * 9 + q) * BN + (tid & 127)] = pc[half * 9 + q];
        }
    };

    unsigned long long acc2[TM][4];
#pragma unroll
    for (int i = 0; i < TM; i++)
#pragma unroll
        for (int j = 0; j < 4; j++) acc2[i][j] = 0ULL;

    loadA(0); loadB(0);
    storeA(0); storeB(0);
    __syncthreads();

    int T = K / BK;
    for (int t = 0; t < T; t++) {
        int buf = t & 1;
        if (t + 1 < T) { loadA((t + 1) * BK); loadB((t + 1) * BK); }

#pragma unroll
        for (int kk = 0; kk < BK; kk++) {
            unsigned long long ad[TM];
#pragma unroll
            for (int h = 0; h < TM / 2; h++) {
                ulonglong2 p = *(const ulonglong2*)
                    &As[buf][kk * BM * 2 + ty * TM * 2 + h * 4];
                ad[2 * h] = p.x; ad[2 * h + 1] = p.y;
            }
            unsigned long long b2[4];
            {
                ulonglong2 p0 = *(const ulonglong2*)&Bs[buf][kk * BN + tx * 8];
                ulonglong2 p1 = *(const ulonglong2*)&Bs[buf][kk * BN + tx * 8 + 4];
                b2[0] = p0.x; b2[1] = p0.y; b2[2] = p1.x; b2[3] = p1.y;
            }
#pragma unroll
            for (int i = 0; i < TM; i++)
#pragma unroll
                for (int jp = 0; jp < 4; jp++) {
                    if (MODE == 0) {
                        asm("fma.rn.f32x2 %0, %1, %2, %0;"
                            : "+l"(acc2[i][jp]) : "l"(ad[i]), "l"(b2[jp]));
                    } else {
                        unsigned long long d;
                        asm("add.rn.f32x2 %0, %1, %2;"
                            : "=l"(d) : "l"(b2[jp]), "l"(ad[i]));
                        d &= 0x7FFFFFFF7FFFFFFFULL;
                        asm("add.rn.f32x2 %0, %0, %1;"
                            : "+l"(acc2[i][jp]) : "l"(d));
                    }
                }
        }

        if (t + 1 < T) { storeA(buf ^ 1); storeB(buf ^ 1); }
        __syncthreads();
    }

    float accf[TM][8];
#pragma unroll
    for (int i = 0; i < TM; i++)
#pragma unroll
        for (int jp = 0; jp < 4; jp++)
            asm("mov.b64 {%0, %1}, %2;"
                : "=f"(accf[i][2*jp]), "=f"(accf[i][2*jp+1]) : "l"(acc2[i][jp]));

#pragma unroll
    for (int i = 0; i < TM; i++) {
        int m = m0 + ty * TM + i;
        if (EPI == 2) {
            float inv  = bg[m] * rsqrtf(bv[m] + 1e-5f);
            float bias = bb[m] - bm[m] * inv;
#pragma unroll
            for (int j = 0; j < 8; j++) {
                int n   = n0 + tx * 8 + j;
                int b_  = n / HWSZ;
                int hw  = n - b_ * HWSZ;
                int idx = (b_ * 512 + m) * HWSZ + hw;
                float v = fmaf(accf[i][j], -inv, bias) + resid[idx];
                Y[idx] = fmaxf(v, 0.0f);
            }
        } else {
            int base = m * NTOT + n0 + tx * 8;
            *(float4*)&Y[base]     = make_float4(accf[i][0], accf[i][1],
                                                 accf[i][2], accf[i][3]);
            *(float4*)&Y[base + 4] = make_float4(accf[i][4], accf[i][5],
                                                 accf[i][6], accf[i][7]);
        }
    }
}

// ---------------------------------------------------------------------------
extern "C" void kernel_launch(void* const* d_in, const int* in_sizes, int n_in,
                              void* d_out, int out_size) {
    const float* x   = (const float*)d_in[0];
    const float* w1s = (const float*)d_in[1];
    const float* w1a = (const float*)d_in[2];
    const float* w2s = (const float*)d_in[3];
    const float* w2a = (const float*)d_in[4];
    const float* w3s = (const float*)d_in[5];
    const float* w3a = (const float*)d_in[6];
    const float* g1 = (const float*)d_in[7],  *b1 = (const float*)d_in[8];
    const float* m1 = (const float*)d_in[9],  *v1 = (const float*)d_in[10];
    const float* g2 = (const float*)d_in[11], *b2 = (const float*)d_in[12];
    const float* m2 = (const float*)d_in[13], *v2 = (const float*)d_in[14];
    const float* g3 = (const float*)d_in[15], *b3 = (const float*)d_in[16];
    const float* m3 = (const float*)d_in[17], *v3 = (const float*)d_in[18];
    float* out = (float*)d_out;

    wprep_all<<<(704512 + 255) / 256, 256>>>(w1s, w1a, w2s, w2a, w3s, w3a);
    bnprep<<<1, 128>>>(g1, b1, m1, v1, g2, b2, m2, v2);
    transpose_x<<<(512 * (NTOT / 4) + 255) / 256, 256>>>(x);

    dim3 gz(98, 4, 2);   // M=128 stages, BM=32, split-K via z
    dim3 gbg(98, 8, 1);  // M=512 stages, BM=64

    // stage 1 shift: K=512 split z=2 x 256 -> t1a/t1b
    gx<32,4,16, 0,0,0,0, 0, 10,0,0, 2,3><<<gz,128>>>(
        nullptr, 128, 256, nullptr, nullptr, nullptr, nullptr, nullptr);
    // stage 1 adder: B = t1a+t1b, K=128 split z=2 x 64 -> u1a/u1b
    gx<32,4,16, 1,0,1,0, 0, 11,2,3, 4,5><<<gz,128>>>(
        nullptr, 128, 64, nullptr, nullptr, nullptr, nullptr, nullptr);
    // stage 2 shift (3x3): B = relu(bn1(-(u1a+u1b))), K=1152 split z=2 x 576
    gx<32,4,18, 0,1,2,1, 0, 12,4,5, 6,7><<<gz,128>>>(
        nullptr, 128, 576, nullptr, nullptr, nullptr, nullptr, nullptr);
    // stage 2 adder (3x3): B = t2a+t2b, K=1152 split z=2 x 576 -> u2a/u2b
    gx<32,4,18, 1,1,1,0, 0, 13,6,7, 8,9><<<gz,128>>>(
        nullptr, 128, 576, nullptr, nullptr, nullptr, nullptr, nullptr);
    // stage 3 shift: B = relu(bn2(-(u2a+u2b))), M=512, K=128 -> t3
    gx<64,8,16, 0,0,2,2, 0, 14,8,9, 1,1><<<gbg,128>>>(
        nullptr, 512, 128, nullptr, nullptr, nullptr, nullptr, nullptr);
    // stage 3 adder: B = t3, K=512, bn3 + resid + relu -> out (NCHW)
    gx<64,8,16, 1,0,0,0, 2, 15,1,1, -1,-1><<<gbg,128>>>(
        out, 512, 512, g3, b3, m3, v3, x);
}

// round 8
// speedup vs baseline: 1.2363x; 1.2328x over previous
#include <cuda_runtime.h>
#include <cstdint>

#define NTOT 12544   // 16 * 784 flattened spatial*batch
#define HWSZ 784
#define WD   28

// ---------------- scratch (device globals; no allocation allowed) ----------
__device__ float g_xT [512 * NTOT];
__device__ float g_A  [512 * NTOT];   // t1 then t3
__device__ float g_B  [128 * NTOT];   // u1 then u2
__device__ float g_C  [128 * NTOT];   // t2
__device__ float g_q1T [512 * 128];   // quantized w1s, k-major
__device__ float g_w1aT[128 * 128];   // w1a k-major, NEGATED
__device__ float g_q2T [1152 * 128];
__device__ float g_w2aT[1152 * 128];  // negated
__device__ float g_q3T [128 * 512];
__device__ float g_w3aT[512 * 512];   // negated

template<int ID>
__device__ __forceinline__ float* gbuf(float* rt) {
    if constexpr (ID == 0) return g_xT;
    else if constexpr (ID == 1) return g_A;
    else if constexpr (ID == 2) return g_B;
    else if constexpr (ID == 3) return g_C;
    else if constexpr (ID == 4) return g_q1T;
    else if constexpr (ID == 5) return g_w1aT;
    else if constexpr (ID == 6) return g_q2T;
    else if constexpr (ID == 7) return g_w2aT;
    else if constexpr (ID == 8) return g_q3T;
    else if constexpr (ID == 9) return g_w3aT;
    else return rt;
}

// ---- weight prep (quantize/negate + k-major transpose), one kernel --------
__device__ __forceinline__ void wp_one(const float* src, float* dst,
                                       int i, int M, int K, int quant, int neg) {
    int m = i / K, k = i - m * K;
    float w = src[i];
    float q = w;
    if (quant) {
        float a = fabsf(w) + 1e-8f;
        q = copysignf(exp2f(rintf(log2f(a))), w);
        if (w == 0.0f) q = 0.0f;   // jnp.sign(0) == 0
    }
    if (neg) q = -q;
    dst[k * M + m] = q;
}

__global__ void wprep_all(const float* __restrict__ w1s, const float* __restrict__ w1a,
                          const float* __restrict__ w2s, const float* __restrict__ w2a,
                          const float* __restrict__ w3s, const float* __restrict__ w3a) {
    int gid = blockIdx.x * blockDim.x + threadIdx.x;
    if (gid < 65536)                 wp_one(w1s, g_q1T,  gid,          128, 512,  1, 0);
    else if (gid < 81920)            wp_one(w1a, g_w1aT, gid - 65536,  128, 128,  0, 1);
    else if (gid < 229376)           wp_one(w2s, g_q2T,  gid - 81920,  128, 1152, 1, 0);
    else if (gid < 376832)           wp_one(w2a, g_w2aT, gid - 229376, 128, 1152, 0, 1);
    else if (gid < 442368)           wp_one(w3s, g_q3T,  gid - 376832, 512, 128,  1, 0);
    else if (gid < 704512)           wp_one(w3a, g_w3aT, gid - 442368, 512, 512,  0, 1);
}

// -------- x: NCHW -> [c][b*784+hw] ----------------------------------------
__global__ void transpose_x(const float* __restrict__ x) {
    int i = blockIdx.x * blockDim.x + threadIdx.x;
    if (i >= 512 * (NTOT / 4)) return;
    int c  = i / (NTOT / 4);
    int r  = i - c * (NTOT / 4);
    int n  = r * 4;
    int b  = n / HWSZ;
    int hw = n - b * HWSZ;
    float4 v = ((const float4*)x)[((b * 512 + c) * HWSZ + hw) >> 2];
    ((float4*)g_xT)[i] = v;
}

// ---- cp.async helpers -----------------------------------------------------
__device__ __forceinline__ uint32_t s2u(const void* p) {
    uint32_t a;
    asm("{ .reg .u64 t; cvta.to.shared.u64 t, %1; cvt.u32.u64 %0, t; }"
        : "=r"(a) : "l"(p));
    return a;
}
__device__ __forceinline__ void cpa16(uint32_t d, const float* s) {
    asm volatile("cp.async.ca.shared.global [%0], [%1], 16;" :: "r"(d), "l"(s));
}
__device__ __forceinline__ void cpa4z(uint32_t d, const float* s, int sz) {
    asm volatile("cp.async.ca.shared.global [%0], [%1], 4, %2;"
                 :: "r"(d), "l"(s), "r"(sz));
}
__device__ __forceinline__ void cp_commit() {
    asm volatile("cp.async.commit_group;");
}
template<int N>
__device__ __forceinline__ void cp_wait() {
    asm volatile("cp.async.wait_group %0;" :: "n"(N));
}

// ---------------------------------------------------------------------------
// GEMM-shaped kernel with S-stage cp.async pipeline. BN=128, NT=128 threads,
// TM x 8 thread tile. A stored non-duplicated; {a,a} pairs built by mov.b64.
//   MODE 0: acc += a*b   MODE 1: acc += |b-a| (A negated; epilogue negates)
//   CONV 0: 1x1 fill (cp.async 16B)  CONV 1: implicit 3x3, zfill halo (BK=18)
//   EPI 0: raw store  EPI 1: relu(bn(-acc))  EPI 2: relu(bn3(-acc)+resid) NCHW
// ---------------------------------------------------------------------------
template<int BM, int TM, int BK, int S, int MODE, int CONV, int EPI,
         int WID, int XID, int YID>
__global__ void __launch_bounds__(128)
gx(float* Yrt, int Mtot, int K,
   const float* __restrict__ bg, const float* __restrict__ bb,
   const float* __restrict__ bm, const float* __restrict__ bv,
   const float* __restrict__ resid)
{
    constexpr int BN = 128, NT = 128;
    static_assert((BM / TM) * 16 == NT, "tile/threads mismatch");
    constexpr int AF4 = BK * BM / 4;
    constexpr int AU  = (AF4 + NT - 1) / NT;
    constexpr int BU  = CONV ? 1 : (BK * BN / 4 / NT);
    const float* Wt = gbuf<WID>(nullptr);
    const float* X  = gbuf<XID>(nullptr);
    float*       Y  = gbuf<YID>(Yrt);

    __shared__ __align__(16) float As[S][BK * BM];
    __shared__ __align__(16) float Bs[S][BK * BN];

    int tid = threadIdx.x;
    int tx  = tid % 16;
    int ty  = tid / 16;
    int m0  = blockIdx.y * BM;
    int n0  = blockIdx.x * BN;

    // conv geometry: loop-invariant halo predicates -> cp.async zfill sizes
    int cn = n0 + tid;
    int coff[9]; int csz[9];
    if (CONV) {
        int cw = cn % WD;
        int ch = (cn / WD) % WD;
#pragma unroll
        for (int q = 0; q < 9; q++) {
            const int r = q / 3, s = q % 3;
            int hh = ch + r - 1, ww = cw + s - 1;
            bool ok = (hh >= 0 && hh < WD && ww >= 0 && ww < WD);
            coff[q] = ok ? (r - 1) * WD + (s - 1) : 0;
            csz[q]  = ok ? 4 : 0;
        }
    }

    const uint32_t AsU = s2u(&As[0][0]);
    const uint32_t BsU = s2u(&Bs[0][0]);
    constexpr int ASTAGE = BK * BM * 4;
    constexpr int BSTAGE = BK * BN * 4;

    auto fill = [&](int t) {
        int st = t % S;
        int k0 = t * BK;
#pragma unroll
        for (int u = 0; u < AU; u++) {
            int v = tid + u * NT;
            if (AF4 % NT == 0 || v < AF4) {
                int kk = v / (BM / 4), mq = v - kk * (BM / 4);
                cpa16(AsU + st * ASTAGE + (kk * BM + mq * 4) * 4,
                      &Wt[(long)(k0 + kk) * Mtot + m0 + mq * 4]);
            }
        }
        if (CONV == 0) {
#pragma unroll
            for (int u = 0; u < BU; u++) {
                int v = tid + u * NT;
                int kk = v / (BN / 4), nq = v - kk * (BN / 4);
                cpa16(BsU + st * BSTAGE + (kk * BN + nq * 4) * 4,
                      &X[(long)(k0 + kk) * NTOT + n0 + nq * 4]);
            }
        } else {
            int c0 = k0 / 9;
#pragma unroll
            for (int half = 0; half < 2; half++) {
                const float* base = &X[(long)(c0 + half) * NTOT + cn];
#pragma unroll
                for (int q = 0; q < 9; q++)
                    cpa4z(BsU + st * BSTAGE + ((half * 9 + q) * BN + tid) * 4,
                          base + coff[q], csz[q]);
            }
        }
    };

    unsigned long long acc2[TM][4];
#pragma unroll
    for (int i = 0; i < TM; i++)
#pragma unroll
        for (int j = 0; j < 4; j++) acc2[i][j] = 0ULL;

    int T = K / BK;
    // prologue: prefetch S-1 stages
#pragma unroll
    for (int p = 0; p < S - 1; p++) {
        if (p < T) fill(p);
        cp_commit();
    }

    for (int t = 0; t < T; t++) {
        cp_wait<S - 2>();
        __syncthreads();
        int tf = t + S - 1;
        if (tf < T) fill(tf);
        cp_commit();

        int st = t % S;
#pragma unroll
        for (int kk = 0; kk < BK; kk++) {
            float a[TM];
            *(float4*)&a[0] = *(const float4*)&As[st][kk * BM + ty * TM];
            if constexpr (TM == 8)
                *(float4*)&a[4] = *(const float4*)&As[st][kk * BM + ty * TM + 4];
            unsigned long long ad[TM];
#pragma unroll
            for (int i = 0; i < TM; i++)
                asm("mov.b64 %0, {%1, %1};" : "=l"(ad[i]) : "f"(a[i]));
            unsigned long long b2[4];
            {
                ulonglong2 p0 = *(const ulonglong2*)&Bs[st][kk * BN + tx * 8];
                ulonglong2 p1 = *(const ulonglong2*)&Bs[st][kk * BN + tx * 8 + 4];
                b2[0] = p0.x; b2[1] = p0.y; b2[2] = p1.x; b2[3] = p1.y;
            }
#pragma unroll
            for (int i = 0; i < TM; i++)
#pragma unroll
                for (int jp = 0; jp < 4; jp++) {
                    if (MODE == 0) {
                        asm("fma.rn.f32x2 %0, %1, %2, %0;"
                            : "+l"(acc2[i][jp]) : "l"(ad[i]), "l"(b2[jp]));
                    } else {
                        unsigned long long d;
                        asm("add.rn.f32x2 %0, %1, %2;"
                            : "=l"(d) : "l"(b2[jp]), "l"(ad[i]));
                        d &= 0x7FFFFFFF7FFFFFFFULL;
                        asm("add.rn.f32x2 %0, %0, %1;"
                            : "+l"(acc2[i][jp]) : "l"(d));
                    }
                }
        }
    }
    cp_wait<0>();

    // ---- unpack + epilogue ----
    float accf[TM][8];
#pragma unroll
    for (int i = 0; i < TM; i++)
#pragma unroll
        for (int jp = 0; jp < 4; jp++)
            asm("mov.b64 {%0, %1}, %2;"
                : "=f"(accf[i][2*jp]), "=f"(accf[i][2*jp+1]) : "l"(acc2[i][jp]));

#pragma unroll
    for (int i = 0; i < TM; i++) {
        int m = m0 + ty * TM + i;
        float inv = 1.0f, bias = 0.0f;
        if (EPI >= 1) {
            inv  = bg[m] * rsqrtf(bv[m] + 1e-5f);
            bias = bb[m] - bm[m] * inv;
        }
        if (EPI == 2) {
#pragma unroll
            for (int j = 0; j < 8; j++) {
                int n   = n0 + tx * 8 + j;
                int b_  = n / HWSZ;
                int hw  = n - b_ * HWSZ;
                int idx = (b_ * 512 + m) * HWSZ + hw;
                float v = fmaf(accf[i][j], -inv, bias) + resid[idx];
                Y[idx] = fmaxf(v, 0.0f);
            }
        } else {
            float o[8];
#pragma unroll
            for (int j = 0; j < 8; j++) {
                float v = (MODE == 0) ? accf[i][j] : -accf[i][j];
                if (EPI == 1) v = fmaxf(fmaf(v, inv, bias), 0.0f);
                o[j] = v;
            }
            int base = m * NTOT + n0 + tx * 8;
            *(float4*)&Y[base]     = make_float4(o[0], o[1], o[2], o[3]);
            *(float4*)&Y[base + 4] = make_float4(o[4], o[5], o[6], o[7]);
        }
    }
}

// ---------------------------------------------------------------------------
extern "C" void kernel_launch(void* const* d_in, const int* in_sizes, int n_in,
                              void* d_out, int out_size) {
    const float* x   = (const float*)d_in[0];
    const float* w1s = (const float*)d_in[1];
    const float* w1a = (const float*)d_in[2];
    const float* w2s = (const float*)d_in[3];
    const float* w2a = (const float*)d_in[4];
    const float* w3s = (const float*)d_in[5];
    const float* w3a = (const float*)d_in[6];
    const float* g1 = (const float*)d_in[7],  *b1 = (const float*)d_in[8];
    const float* m1 = (const float*)d_in[9],  *v1 = (const float*)d_in[10];
    const float* g2 = (const float*)d_in[11], *b2 = (const float*)d_in[12];
    const float* m2 = (const float*)d_in[13], *v2 = (const float*)d_in[14];
    const float* g3 = (const float*)d_in[15], *b3 = (const float*)d_in[16];
    const float* m3 = (const float*)d_in[17], *v3 = (const float*)d_in[18];
    float* out = (float*)d_out;

    wprep_all<<<(704512 + 255) / 256, 256>>>(w1s, w1a, w2s, w2a, w3s, w3a);
    transpose_x<<<(512 * (NTOT / 4) + 255) / 256, 256>>>(x);

    dim3 gsm(98, 4);   // M=128 stages, BM=32
    dim3 gbg(98, 8);   // M=512 stages, BM=64

    // stage 1: shift 1x1 (K=512) -> t1 (g_A)
    gx<32,4,16,4, 0,0,0, 4,0,1><<<gsm,128>>>(
        nullptr, 128, 512, nullptr, nullptr, nullptr, nullptr, nullptr);
    // stage 1: adder 1x1 + BN1 + ReLU -> u1 (g_B)
    gx<32,4,16,4, 1,0,1, 5,1,2><<<gsm,128>>>(
        nullptr, 128, 128, g1, b1, m1, v1, nullptr);

    // stage 2: shift 3x3 (K=1152, BK=18) -> t2 (g_C)
    gx<32,4,18,4, 0,1,0, 6,2,3><<<gsm,128>>>(
        nullptr, 128, 1152, nullptr, nullptr, nullptr, nullptr, nullptr);
    // stage 2: adder 3x3 + BN2 + ReLU -> u2 (g_B)
    gx<32,4,18,4, 1,1,1, 7,3,2><<<gsm,128>>>(
        nullptr, 128, 1152, g2, b2, m2, v2, nullptr);

    // stage 3: shift 1x1 (M=512, K=128) -> t3 (g_A)
    gx<64,8,16,3, 0,0,0, 8,2,1><<<gbg,128>>>(
        nullptr, 512, 128, nullptr, nullptr, nullptr, nullptr, nullptr);
    // stage 3: adder 1x1 (K=512) + BN3 + resid + ReLU -> out (NCHW)
    gx<64,8,16,3, 1,0,2, 9,1,-1><<<gbg,128>>>(
        out, 512, 512, g3, b3, m3, v3, x);
}